// round 15
// baseline (speedup 1.0000x reference)
#include <cuda_runtime.h>
#include <cuda_bf16.h>
#include <math.h>
#include <stdint.h>

#define Bsz   4
#define C     768
#define HEADS 12
#define HDIM  64
#define NTOK  (Bsz*64*64)        // 16384
#define C7    (7*C)              // 5376
#define FFDIM (4*C)              // 3072
#define QKV   (3*C)              // 2304
#define CAT   (C + FFDIM)        // 3840

// ---------------- scratch (static device globals) ---------------------------
__device__ __nv_bfloat16 g_projb[(size_t)NTOK * QKV];   // q|k|v bf16
__device__ __nv_bfloat16 g_xn_bf [(size_t)NTOK * C];    // LN(x) bf16
__device__ __nv_bfloat16 g_cat   [(size_t)NTOK * CAT];  // [attnO | gelu(ff)] bf16
__device__ __nv_bfloat16 g_Wqkv_t[(size_t)C7 * C];      // Wqkv^T bf16  [n][k]
__device__ __nv_bfloat16 g_Wcat_t[(size_t)C * CAT];     // [Wout;Wmlp]^T bf16 [n][k]

__device__ __forceinline__ uint32_t smem_u32(const void* p) {
    uint32_t a;
    asm("{ .reg .u64 t; cvta.to.shared.u64 t, %1; cvt.u32.u64 %0, t; }"
        : "=r"(a) : "l"(p));
    return a;
}

// ---------------- weight transpose+convert: out[n][k] = in[k][n] ------------
__global__ void transpose_w(const float* __restrict__ in, __nv_bfloat16* __restrict__ out,
                            int N, int ldout, int koff) {
    __shared__ float tile[32][33];
    int n0 = blockIdx.x * 32, k0 = blockIdx.y * 32;
    int tx = threadIdx.x, ty = threadIdx.y;
    #pragma unroll
    for (int r = 0; r < 32; r += 8)
        tile[ty + r][tx] = in[(size_t)(k0 + ty + r) * N + n0 + tx];
    __syncthreads();
    #pragma unroll
    for (int r = 0; r < 32; r += 8)
        out[(size_t)(n0 + ty + r) * ldout + koff + k0 + tx] =
            __float2bfloat16(tile[tx][ty + r]);
}

// ---------------- block reduction helper ------------------------------------
__device__ __forceinline__ float block_sum256(float v) {
    __shared__ float sh[8];
    int lane = threadIdx.x & 31, w = threadIdx.x >> 5;
    #pragma unroll
    for (int o = 16; o; o >>= 1) v += __shfl_xor_sync(0xFFFFFFFFu, v, o);
    if (lane == 0) sh[w] = v;
    __syncthreads();
    float r = (lane < 8) ? sh[lane] : 0.f;
    if (w == 0) {
        #pragma unroll
        for (int o = 4; o; o >>= 1) r += __shfl_xor_sync(0xFFFFFFFFu, r, o);
        if (lane == 0) sh[0] = r;
    }
    __syncthreads();
    float out = sh[0];
    __syncthreads();
    return out;
}

// ---------------- 1. LayerNorm over C=768, writes bf16 ----------------------
__global__ void ln_kernel(const float* __restrict__ x,
                          const float* __restrict__ w) {
    int t = blockIdx.x;
    const float* xr = x + (size_t)t * C;
    float v[3];
    float s = 0.f;
    #pragma unroll
    for (int i = 0; i < 3; i++) { v[i] = xr[threadIdx.x + i * 256]; s += v[i]; }
    s = block_sum256(s);
    float mu = s * (1.f / C);
    float vs = 0.f;
    #pragma unroll
    for (int i = 0; i < 3; i++) { float d = v[i] - mu; vs += d * d; }
    vs = block_sum256(vs);
    float inv = rsqrtf(vs * (1.f / C) + 1e-5f);
    #pragma unroll
    for (int i = 0; i < 3; i++) {
        int c = threadIdx.x + i * 256;
        g_xn_bf[(size_t)t * C + c] = __float2bfloat16((v[i] - mu) * inv * w[c]);
    }
}

// ---------------- 2. bf16 mma GEMM: 128x128 tile, 4-stage, 1 sync/iter ------
#define BM 128
#define BN 128
#define TST 40   // k-stride in bf16 (32 + 8 pad)
#define A_ST (BM * TST)
#define B_ST (BN * TST)
#define NSTAGE 4
#define SMEM_BYTES (NSTAGE * (A_ST + B_ST) * 2)   // 81920

__device__ __forceinline__ float gelu_exact(float v) {
    return 0.5f * v * (1.f + erff(v * 0.70710678118654752f));
}

#define MMA16816(d, a, b0v, b1v) \
    asm volatile( \
        "mma.sync.aligned.m16n8k16.row.col.f32.bf16.bf16.f32 " \
        "{%0,%1,%2,%3}, {%4,%5,%6,%7}, {%8,%9}, {%0,%1,%2,%3};" \
        : "+f"((d)[0]), "+f"((d)[1]), "+f"((d)[2]), "+f"((d)[3]) \
        : "r"((a)[0]), "r"((a)[1]), "r"((a)[2]), "r"((a)[3]), \
          "r"(b0v), "r"(b1v))

__global__ void __launch_bounds__(256) hgemm(
        const __nv_bfloat16* __restrict__ A, int lda,
        const __nv_bfloat16* __restrict__ Bt, int ldb, int K,
        const float* __restrict__ bias1, const float* __restrict__ bias2,
        const float* __restrict__ xres, const float* __restrict__ gamma,
        float* __restrict__ outp, int mode) {
    extern __shared__ __align__(16) __nv_bfloat16 SM[];
    uint32_t smb = smem_u32(SM);

    int tid = threadIdx.x;
    int bm = blockIdx.y * BM, bn = blockIdx.x * BN;
    int w = tid >> 5, lane = tid & 31;
    int wm = (w & 1) * 64, wn = (w >> 1) * 32;
    int grp = lane >> 2, tq = lane & 3;

    float acc[4][4][4];
    #pragma unroll
    for (int i = 0; i < 4; i++)
        #pragma unroll
        for (int j = 0; j < 4; j++)
            #pragma unroll
            for (int k = 0; k < 4; k++) acc[i][j][k] = 0.f;

    #define CP16(sa, ga) \
        asm volatile("cp.async.cg.shared.global [%0], [%1], 16;" :: "r"(sa), "l"(ga))
    #define CP_COMMIT() asm volatile("cp.async.commit_group;" ::: "memory")

    #define LOAD_STAGE(s, kt) do {                                              \
        _Pragma("unroll")                                                       \
        for (int i = 0; i < 2; i++) {                                           \
            int idx = tid + i * 256;                                            \
            uint32_t sa = smb + (uint32_t)((s) * A_ST + (idx >> 2) * TST + (idx & 3) * 8) * 2; \
            CP16(sa, A + (size_t)(bm + (idx >> 2)) * lda + (kt) * 32 + (idx & 3) * 8); \
        }                                                                       \
        _Pragma("unroll")                                                       \
        for (int i = 0; i < 2; i++) {                                           \
            int idx = tid + i * 256;                                            \
            uint32_t sa = smb + (uint32_t)(NSTAGE * A_ST + (s) * B_ST + (idx >> 2) * TST + (idx & 3) * 8) * 2; \
            CP16(sa, Bt + (size_t)(bn + (idx >> 2)) * ldb + (kt) * 32 + (idx & 3) * 8); \
        }                                                                       \
        CP_COMMIT();                                                            \
    } while (0)

    #define COMPUTE_STAGE(s) do {                                               \
        _Pragma("unroll")                                                       \
        for (int ks = 0; ks < 2; ks++) {                                        \
            int kk = ks * 16;                                                   \
            unsigned a[4][4], b[4][2];                                          \
            _Pragma("unroll")                                                   \
            for (int mt = 0; mt < 4; mt++) {                                    \
                int row = wm + mt * 16 + (lane & 7) + ((lane >> 3) & 1) * 8;    \
                int col = kk + (lane >> 4) * 8;                                 \
                uint32_t ad = smb + (uint32_t)((s) * A_ST + row * TST + col) * 2; \
                asm volatile("ldmatrix.sync.aligned.m8n8.x4.shared.b16 {%0,%1,%2,%3}, [%4];" \
                             : "=r"(a[mt][0]), "=r"(a[mt][1]), "=r"(a[mt][2]), "=r"(a[mt][3]) \
                             : "r"(ad));                                        \
            }                                                                   \
            _Pragma("unroll")                                                   \
            for (int p = 0; p < 2; p++) {                                       \
                int nrow = wn + p * 16 + (lane & 7) + ((lane >> 4) & 1) * 8;    \
                int col = kk + ((lane >> 3) & 1) * 8;                           \
                uint32_t bd = smb + (uint32_t)(NSTAGE * A_ST + (s) * B_ST + nrow * TST + col) * 2; \
                asm volatile("ldmatrix.sync.aligned.m8n8.x4.shared.b16 {%0,%1,%2,%3}, [%4];" \
                             : "=r"(b[2*p][0]), "=r"(b[2*p][1]), "=r"(b[2*p+1][0]), "=r"(b[2*p+1][1]) \
                             : "r"(bd));                                        \
            }                                                                   \
            _Pragma("unroll")                                                   \
            for (int mt = 0; mt < 4; mt++)                                      \
                _Pragma("unroll")                                               \
                for (int nt = 0; nt < 4; nt++)                                  \
                    MMA16816(acc[mt][nt], a[mt], b[nt][0], b[nt][1]);           \
        }                                                                       \
    } while (0)

    int KT = K / 32;   // 24 or 120 (>= 4)
    LOAD_STAGE(0, 0);
    LOAD_STAGE(1, 1);
    LOAD_STAGE(2, 2);

    for (int kt = 0; kt < KT - 3; kt++) {
        asm volatile("cp.async.wait_group 2;" ::: "memory");
        __syncthreads();
        LOAD_STAGE((kt + 3) & 3, kt + 3);
        COMPUTE_STAGE(kt & 3);
    }
    asm volatile("cp.async.wait_group 2;" ::: "memory");
    __syncthreads();
    COMPUTE_STAGE((KT - 3) & 3);
    asm volatile("cp.async.wait_group 1;" ::: "memory");
    __syncthreads();
    COMPUTE_STAGE((KT - 2) & 3);
    asm volatile("cp.async.wait_group 0;" ::: "memory");
    __syncthreads();
    COMPUTE_STAGE((KT - 1) & 3);

    #pragma unroll
    for (int mt = 0; mt < 4; mt++) {
        #pragma unroll
        for (int nt = 0; nt < 4; nt++) {
            int row0 = bm + wm + mt * 16 + grp;
            int col  = bn + wn + nt * 8 + tq * 2;
            #pragma unroll
            for (int half = 0; half < 2; half++) {
                int row = row0 + half * 8;
                float v0 = acc[mt][nt][half * 2 + 0];
                float v1 = acc[mt][nt][half * 2 + 1];
                if (mode == 0) {
                    v0 += bias1[col]; v1 += bias1[col + 1];
                    if (col < QKV) {
                        __nv_bfloat162 h = __floats2bfloat162_rn(v0, v1);
                        *(unsigned*)&g_projb[(size_t)row * QKV + col] = *(unsigned*)&h;
                    } else {
                        __nv_bfloat162 h = __floats2bfloat162_rn(gelu_exact(v0), gelu_exact(v1));
                        *(unsigned*)&g_cat[(size_t)row * CAT + col - 1536] = *(unsigned*)&h;
                    }
                } else {
                    size_t p = (size_t)row * C + col;
                    outp[p]     = xres[p]     + gamma[col]     * (v0 + bias1[col]     + bias2[col]);
                    outp[p + 1] = xres[p + 1] + gamma[col + 1] * (v1 + bias1[col + 1] + bias2[col + 1]);
                }
            }
        }
    }
}

// ---------------- 3. FUSED axial attention (both axes, one kernel) ----------
// V prefetched to registers before the S phase (hidden under MMAs+softmax);
// O accumulates in registers across both axes.
#define QST 72   // bf16 row stride (64 + 8 pad)

__global__ void __launch_bounds__(128) attn_fused(const float* __restrict__ qw,
                                                  const float* __restrict__ kw) {
    __shared__ __align__(16) __nv_bfloat16 Qs[64 * QST];  // Q (pre-scaled), later V^T
    __shared__ __align__(16) __nv_bfloat16 Ks[64 * QST];  // K
    int head = blockIdx.x % HEADS;
    int line = (blockIdx.x / HEADS) % 64;
    int b    = blockIdx.x / (HEADS * 64);
    int tid  = threadIdx.x, lane = tid & 31, warp = tid >> 5;
    int grp = lane >> 2, tq = lane & 3;
    int row0 = warp * 16;

    float o[8][4];
    #pragma unroll
    for (int nt = 0; nt < 8; nt++)
        #pragma unroll
        for (int j = 0; j < 4; j++) o[nt][j] = 0.f;

    #pragma unroll
    for (int axis = 0; axis < 2; axis++) {
        #define TOKA(pos) (axis == 0 ? ((b * 64 + line) * 64 + (pos)) : ((b * 64 + (pos)) * 64 + line))

        // ---- prefetch V into registers ----
        uint4 vreg[4];
        #pragma unroll
        for (int it = 0; it < 4; it++) {
            int chunk = tid + it * 128;
            int pos = chunk >> 3, c8 = (chunk & 7) * 8;
            vreg[it] = *(const uint4*)(g_projb + (size_t)TOKA(pos) * QKV + 2 * C + head * HDIM + c8);
        }

        // ---- Q then K: load + per-head LN (2 threads/row, 32 elems each) ----
        {
            int row = tid >> 1, seg = tid & 1;
            const __nv_bfloat16* gq = g_projb + (size_t)TOKA(row) * QKV + head * HDIM + seg * 32;
            {
                float q[32];
                #pragma unroll
                for (int i = 0; i < 4; i++) {
                    uint4 u = *(const uint4*)(gq + i * 8);
                    const __nv_bfloat162* p2 = (const __nv_bfloat162*)&u;
                    #pragma unroll
                    for (int j = 0; j < 4; j++) {
                        float2 f = __bfloat1622float2(p2[j]);
                        q[i*8 + j*2] = f.x; q[i*8 + j*2 + 1] = f.y;
                    }
                }
                float s1 = 0.f, s2 = 0.f;
                #pragma unroll
                for (int e = 0; e < 32; e++) { s1 += q[e]; s2 += q[e]*q[e]; }
                s1 += __shfl_xor_sync(0xFFFFFFFFu, s1, 1);
                s2 += __shfl_xor_sync(0xFFFFFFFFu, s2, 1);
                float mu = s1 * (1.f/64.f);
                float inv = rsqrtf(s2 * (1.f/64.f) - mu * mu + 1e-5f) * 0.125f;
                #pragma unroll
                for (int e = 0; e < 32; e += 2) {
                    int c = seg * 32 + e;
                    __nv_bfloat162 h = __floats2bfloat162_rn((q[e] - mu) * inv * __ldg(qw + c),
                                                             (q[e+1] - mu) * inv * __ldg(qw + c + 1));
                    *(unsigned*)&Qs[row * QST + c] = *(unsigned*)&h;
                }
            }
            {
                float k[32];
                #pragma unroll
                for (int i = 0; i < 4; i++) {
                    uint4 u = *(const uint4*)(gq + C + i * 8);
                    const __nv_bfloat162* p2 = (const __nv_bfloat162*)&u;
                    #pragma unroll
                    for (int j = 0; j < 4; j++) {
                        float2 f = __bfloat1622float2(p2[j]);
                        k[i*8 + j*2] = f.x; k[i*8 + j*2 + 1] = f.y;
                    }
                }
                float s1 = 0.f, s2 = 0.f;
                #pragma unroll
                for (int e = 0; e < 32; e++) { s1 += k[e]; s2 += k[e]*k[e]; }
                s1 += __shfl_xor_sync(0xFFFFFFFFu, s1, 1);
                s2 += __shfl_xor_sync(0xFFFFFFFFu, s2, 1);
                float mu = s1 * (1.f/64.f);
                float inv = rsqrtf(s2 * (1.f/64.f) - mu * mu + 1e-5f);
                #pragma unroll
                for (int e = 0; e < 32; e += 2) {
                    int c = seg * 32 + e;
                    __nv_bfloat162 h = __floats2bfloat162_rn((k[e] - mu) * inv * __ldg(kw + c),
                                                             (k[e+1] - mu) * inv * __ldg(kw + c + 1));
                    *(unsigned*)&Ks[row * QST + c] = *(unsigned*)&h;
                }
            }
        }
        __syncthreads();

        // ---- S = Q K^T ----
        float s[8][4];
        #pragma unroll
        for (int nt = 0; nt < 8; nt++)
            #pragma unroll
            for (int j = 0; j < 4; j++) s[nt][j] = 0.f;
        #pragma unroll
        for (int kt = 0; kt < 4; kt++) {
            unsigned a[4];
            const __nv_bfloat16* qb = &Qs[(row0 + grp) * QST + kt * 16 + tq * 2];
            a[0] = *(const unsigned*)(qb);
            a[1] = *(const unsigned*)(qb + 8 * QST);
            a[2] = *(const unsigned*)(qb + 8);
            a[3] = *(const unsigned*)(qb + 8 * QST + 8);
            #pragma unroll
            for (int nt = 0; nt < 8; nt++) {
                const __nv_bfloat16* kb = &Ks[(nt * 8 + grp) * QST + kt * 16 + tq * 2];
                unsigned b0 = *(const unsigned*)(kb);
                unsigned b1 = *(const unsigned*)(kb + 8);
                MMA16816(s[nt], a, b0, b1);
            }
        }

        // ---- softmax ----
        float m0 = -1e30f, m1 = -1e30f;
        #pragma unroll
        for (int nt = 0; nt < 8; nt++) {
            m0 = fmaxf(m0, fmaxf(s[nt][0], s[nt][1]));
            m1 = fmaxf(m1, fmaxf(s[nt][2], s[nt][3]));
        }
        #pragma unroll
        for (int oo = 1; oo <= 2; oo <<= 1) {
            m0 = fmaxf(m0, __shfl_xor_sync(0xFFFFFFFFu, m0, oo));
            m1 = fmaxf(m1, __shfl_xor_sync(0xFFFFFFFFu, m1, oo));
        }
        float r0 = 0.f, r1 = 0.f;
        #pragma unroll
        for (int nt = 0; nt < 8; nt++) {
            s[nt][0] = __expf(s[nt][0] - m0); s[nt][1] = __expf(s[nt][1] - m0);
            s[nt][2] = __expf(s[nt][2] - m1); s[nt][3] = __expf(s[nt][3] - m1);
            r0 += s[nt][0] + s[nt][1];
            r1 += s[nt][2] + s[nt][3];
        }
        #pragma unroll
        for (int oo = 1; oo <= 2; oo <<= 1) {
            r0 += __shfl_xor_sync(0xFFFFFFFFu, r0, oo);
            r1 += __shfl_xor_sync(0xFFFFFFFFu, r1, oo);
        }
        float inv0 = 1.f / r0, inv1 = 1.f / r1;

        // ---- pack P to bf16 A-fragments ----
        unsigned pf[4][4];
        #pragma unroll
        for (int kt = 0; kt < 4; kt++) {
            __nv_bfloat162 h;
            h = __floats2bfloat162_rn(s[2*kt][0] * inv0, s[2*kt][1] * inv0);     pf[kt][0] = *(unsigned*)&h;
            h = __floats2bfloat162_rn(s[2*kt][2] * inv1, s[2*kt][3] * inv1);     pf[kt][1] = *(unsigned*)&h;
            h = __floats2bfloat162_rn(s[2*kt+1][0] * inv0, s[2*kt+1][1] * inv0); pf[kt][2] = *(unsigned*)&h;
            h = __floats2bfloat162_rn(s[2*kt+1][2] * inv1, s[2*kt+1][3] * inv1); pf[kt][3] = *(unsigned*)&h;
        }

        // ---- Qs dead: store prefetched V transposed into it ----
        __syncthreads();
        #pragma unroll
        for (int it = 0; it < 4; it++) {
            int chunk = tid + it * 128;
            int pos = chunk >> 3, c8 = (chunk & 7) * 8;
            const __nv_bfloat16* e = (const __nv_bfloat16*)&vreg[it];
            #pragma unroll
            for (int j = 0; j < 8; j++)
                Qs[(c8 + j) * QST + pos] = e[j];
        }
        __syncthreads();

        // ---- O += P V ----
        #pragma unroll
        for (int kt = 0; kt < 4; kt++) {
            #pragma unroll
            for (int nt = 0; nt < 8; nt++) {
                const __nv_bfloat16* vb = &Qs[(nt * 8 + grp) * QST + kt * 16 + tq * 2];
                unsigned b0 = *(const unsigned*)(vb);
                unsigned b1 = *(const unsigned*)(vb + 8);
                MMA16816(o[nt], pf[kt], b0, b1);
            }
        }
        __syncthreads();   // protect Qs/Ks before next axis reloads them
        #undef TOKA
    }

    // ---- write combined O (fp32 accumulated across axes) -> g_cat bf16 ----
    #pragma unroll
    for (int half = 0; half < 2; half++) {
        int qrow = row0 + grp + half * 8;
        size_t tok = (size_t)((b * 64 + qrow) * 64 + line);
        #pragma unroll
        for (int nt = 0; nt < 8; nt++) {
            int col = head * HDIM + nt * 8 + tq * 2;
            __nv_bfloat162 h = __floats2bfloat162_rn(o[nt][half * 2 + 0], o[nt][half * 2 + 1]);
            *(unsigned*)&g_cat[tok * CAT + col] = *(unsigned*)&h;
        }
    }
}

// ---------------- launch ----------------------------------------------------
extern "C" void kernel_launch(void* const* d_in, const int* in_sizes, int n_in,
                              void* d_out, int out_size) {
    const float* x      = (const float*)d_in[0];
    const float* norm_w = (const float*)d_in[1];
    const float* Wqkv   = (const float*)d_in[2];
    const float* bqkv   = (const float*)d_in[3];
    const float* qnw    = (const float*)d_in[4];
    const float* knw    = (const float*)d_in[5];
    const float* Wout   = (const float*)d_in[6];
    const float* bout   = (const float*)d_in[7];
    const float* Wmlp   = (const float*)d_in[8];
    const float* bmlp   = (const float*)d_in[9];
    const float* gamma  = (const float*)d_in[10];
    float* out = (float*)d_out;

    void *p_xnb, *p_cat, *p_wq, *p_wc;
    cudaGetSymbolAddress(&p_xnb, g_xn_bf);
    cudaGetSymbolAddress(&p_cat, g_cat);
    cudaGetSymbolAddress(&p_wq,  g_Wqkv_t);
    cudaGetSymbolAddress(&p_wc,  g_Wcat_t);

    cudaFuncSetAttribute(hgemm, cudaFuncAttributeMaxDynamicSharedMemorySize, SMEM_BYTES);

    // 0. transpose+convert weights
    transpose_w<<<dim3(C7 / 32, C / 32), dim3(32, 8)>>>(Wqkv, (__nv_bfloat16*)p_wq, C7, C, 0);
    transpose_w<<<dim3(C / 32, C / 32), dim3(32, 8)>>>(Wout, (__nv_bfloat16*)p_wc, C, CAT, 0);
    transpose_w<<<dim3(C / 32, FFDIM / 32), dim3(32, 8)>>>(Wmlp, (__nv_bfloat16*)p_wc, C, CAT, C);

    // 1. LayerNorm -> bf16 xn
    ln_kernel<<<NTOK, 256>>>(x, norm_w);

    // 2. fused qkv+ff GEMM (q,k,v bf16 -> g_projb; gelu(ff) bf16 -> g_cat)
    hgemm<<<dim3(C7 / BN, NTOK / BM), 256, SMEM_BYTES>>>(
        (const __nv_bfloat16*)p_xnb, C, (const __nv_bfloat16*)p_wq, C,
        C, bqkv, nullptr, nullptr, nullptr, nullptr, 0);

    // 3. fused axial attention (both axes, O accumulated in registers)
    attn_fused<<<Bsz * 64 * HEADS, 128>>>(qnw, knw);

    // 4. fused output GEMM + residual epilogue
    hgemm<<<dim3(C / BN, NTOK / BM), 256, SMEM_BYTES>>>(
        (const __nv_bfloat16*)p_cat, CAT, (const __nv_bfloat16*)p_wc, CAT,
        CAT, bout, bmlp, x, gamma, out, 1);
}

// round 16
// speedup vs baseline: 1.0127x; 1.0127x over previous
#include <cuda_runtime.h>
#include <cuda_bf16.h>
#include <math.h>
#include <stdint.h>

#define Bsz   4
#define C     768
#define HEADS 12
#define HDIM  64
#define NTOK  (Bsz*64*64)        // 16384
#define C7    (7*C)              // 5376
#define FFDIM (4*C)              // 3072
#define QKV   (3*C)              // 2304
#define CAT   (C + FFDIM)        // 3840

// ---------------- scratch (static device globals) ---------------------------
__device__ __nv_bfloat16 g_projb[(size_t)NTOK * QKV];   // q|k|v bf16
__device__ __nv_bfloat16 g_xn_bf [(size_t)NTOK * C];    // LN(x) bf16
__device__ __nv_bfloat16 g_cat   [(size_t)NTOK * CAT];  // [attnO | gelu(ff)] bf16
__device__ __nv_bfloat16 g_Wqkv_t[(size_t)C7 * C];      // Wqkv^T bf16  [n][k]
__device__ __nv_bfloat16 g_Wcat_t[(size_t)C * CAT];     // [Wout;Wmlp]^T bf16 [n][k]

__device__ __forceinline__ uint32_t smem_u32(const void* p) {
    uint32_t a;
    asm("{ .reg .u64 t; cvta.to.shared.u64 t, %1; cvt.u32.u64 %0, t; }"
        : "=r"(a) : "l"(p));
    return a;
}

// ---------------- weight transpose+convert: out[n][k] = in[k][n] ------------
__global__ void transpose_w(const float* __restrict__ in, __nv_bfloat16* __restrict__ out,
                            int N, int ldout, int koff) {
    __shared__ float tile[32][33];
    int n0 = blockIdx.x * 32, k0 = blockIdx.y * 32;
    int tx = threadIdx.x, ty = threadIdx.y;
    #pragma unroll
    for (int r = 0; r < 32; r += 8)
        tile[ty + r][tx] = in[(size_t)(k0 + ty + r) * N + n0 + tx];
    __syncthreads();
    #pragma unroll
    for (int r = 0; r < 32; r += 8)
        out[(size_t)(n0 + ty + r) * ldout + koff + k0 + tx] =
            __float2bfloat16(tile[tx][ty + r]);
}

// ---------------- 1. LayerNorm over C=768 (192 thr, float4) -> bf16 ---------
__global__ void __launch_bounds__(192) ln_kernel(const float* __restrict__ x,
                                                 const float* __restrict__ w) {
    __shared__ float sh[6];
    int t = blockIdx.x, tid = threadIdx.x;
    int lane = tid & 31, wp = tid >> 5;
    float4 v = *(const float4*)(x + (size_t)t * C + tid * 4);

    float s = v.x + v.y + v.z + v.w;
    #pragma unroll
    for (int o = 16; o; o >>= 1) s += __shfl_xor_sync(0xFFFFFFFFu, s, o);
    if (lane == 0) sh[wp] = s;
    __syncthreads();
    float tot = sh[0] + sh[1] + sh[2] + sh[3] + sh[4] + sh[5];
    float mu = tot * (1.f / C);
    __syncthreads();

    float d0 = v.x - mu, d1 = v.y - mu, d2 = v.z - mu, d3 = v.w - mu;
    float vs = d0*d0 + d1*d1 + d2*d2 + d3*d3;
    #pragma unroll
    for (int o = 16; o; o >>= 1) vs += __shfl_xor_sync(0xFFFFFFFFu, vs, o);
    if (lane == 0) sh[wp] = vs;
    __syncthreads();
    float vtot = sh[0] + sh[1] + sh[2] + sh[3] + sh[4] + sh[5];
    float inv = rsqrtf(vtot * (1.f / C) + 1e-5f);

    int c = tid * 4;
    float4 wv = *(const float4*)(w + c);
    __nv_bfloat162 h0 = __floats2bfloat162_rn(d0 * inv * wv.x, d1 * inv * wv.y);
    __nv_bfloat162 h1 = __floats2bfloat162_rn(d2 * inv * wv.z, d3 * inv * wv.w);
    uint2 u;
    u.x = *(unsigned*)&h0; u.y = *(unsigned*)&h1;
    *(uint2*)&g_xn_bf[(size_t)t * C + c] = u;
}

// ---------------- 2. bf16 mma GEMM: 128x128 tile, 4-stage, 1 sync/iter ------
#define BM 128
#define BN 128
#define TST 40   // k-stride in bf16 (32 + 8 pad)
#define A_ST (BM * TST)
#define B_ST (BN * TST)
#define NSTAGE 4
#define SMEM_BYTES (NSTAGE * (A_ST + B_ST) * 2)   // 81920

__device__ __forceinline__ float gelu_exact(float v) {
    return 0.5f * v * (1.f + erff(v * 0.70710678118654752f));
}

#define MMA16816(d, a, b0v, b1v) \
    asm volatile( \
        "mma.sync.aligned.m16n8k16.row.col.f32.bf16.bf16.f32 " \
        "{%0,%1,%2,%3}, {%4,%5,%6,%7}, {%8,%9}, {%0,%1,%2,%3};" \
        : "+f"((d)[0]), "+f"((d)[1]), "+f"((d)[2]), "+f"((d)[3]) \
        : "r"((a)[0]), "r"((a)[1]), "r"((a)[2]), "r"((a)[3]), \
          "r"(b0v), "r"(b1v))

__global__ void __launch_bounds__(256) hgemm(
        const __nv_bfloat16* __restrict__ A, int lda,
        const __nv_bfloat16* __restrict__ Bt, int ldb, int K,
        const float* __restrict__ bias1, const float* __restrict__ bias2,
        const float* __restrict__ xres, const float* __restrict__ gamma,
        float* __restrict__ outp, int mode) {
    extern __shared__ __align__(16) __nv_bfloat16 SM[];
    uint32_t smb = smem_u32(SM);

    int tid = threadIdx.x;
    int bm = blockIdx.y * BM, bn = blockIdx.x * BN;
    int w = tid >> 5, lane = tid & 31;
    int wm = (w & 1) * 64, wn = (w >> 1) * 32;
    int grp = lane >> 2, tq = lane & 3;

    float acc[4][4][4];
    #pragma unroll
    for (int i = 0; i < 4; i++)
        #pragma unroll
        for (int j = 0; j < 4; j++)
            #pragma unroll
            for (int k = 0; k < 4; k++) acc[i][j][k] = 0.f;

    #define CP16(sa, ga) \
        asm volatile("cp.async.cg.shared.global [%0], [%1], 16;" :: "r"(sa), "l"(ga))
    #define CP_COMMIT() asm volatile("cp.async.commit_group;" ::: "memory")

    #define LOAD_STAGE(s, kt) do {                                              \
        _Pragma("unroll")                                                       \
        for (int i = 0; i < 2; i++) {                                           \
            int idx = tid + i * 256;                                            \
            uint32_t sa = smb + (uint32_t)((s) * A_ST + (idx >> 2) * TST + (idx & 3) * 8) * 2; \
            CP16(sa, A + (size_t)(bm + (idx >> 2)) * lda + (kt) * 32 + (idx & 3) * 8); \
        }                                                                       \
        _Pragma("unroll")                                                       \
        for (int i = 0; i < 2; i++) {                                           \
            int idx = tid + i * 256;                                            \
            uint32_t sa = smb + (uint32_t)(NSTAGE * A_ST + (s) * B_ST + (idx >> 2) * TST + (idx & 3) * 8) * 2; \
            CP16(sa, Bt + (size_t)(bn + (idx >> 2)) * ldb + (kt) * 32 + (idx & 3) * 8); \
        }                                                                       \
        CP_COMMIT();                                                            \
    } while (0)

    #define COMPUTE_STAGE(s) do {                                               \
        _Pragma("unroll")                                                       \
        for (int ks = 0; ks < 2; ks++) {                                        \
            int kk = ks * 16;                                                   \
            unsigned a[4][4], b[4][2];                                          \
            _Pragma("unroll")                                                   \
            for (int mt = 0; mt < 4; mt++) {                                    \
                int row = wm + mt * 16 + (lane & 7) + ((lane >> 3) & 1) * 8;    \
                int col = kk + (lane >> 4) * 8;                                 \
                uint32_t ad = smb + (uint32_t)((s) * A_ST + row * TST + col) * 2; \
                asm volatile("ldmatrix.sync.aligned.m8n8.x4.shared.b16 {%0,%1,%2,%3}, [%4];" \
                             : "=r"(a[mt][0]), "=r"(a[mt][1]), "=r"(a[mt][2]), "=r"(a[mt][3]) \
                             : "r"(ad));                                        \
            }                                                                   \
            _Pragma("unroll")                                                   \
            for (int p = 0; p < 2; p++) {                                       \
                int nrow = wn + p * 16 + (lane & 7) + ((lane >> 4) & 1) * 8;    \
                int col = kk + ((lane >> 3) & 1) * 8;                           \
                uint32_t bd = smb + (uint32_t)(NSTAGE * A_ST + (s) * B_ST + nrow * TST + col) * 2; \
                asm volatile("ldmatrix.sync.aligned.m8n8.x4.shared.b16 {%0,%1,%2,%3}, [%4];" \
                             : "=r"(b[2*p][0]), "=r"(b[2*p][1]), "=r"(b[2*p+1][0]), "=r"(b[2*p+1][1]) \
                             : "r"(bd));                                        \
            }                                                                   \
            _Pragma("unroll")                                                   \
            for (int mt = 0; mt < 4; mt++)                                      \
                _Pragma("unroll")                                               \
                for (int nt = 0; nt < 4; nt++)                                  \
                    MMA16816(acc[mt][nt], a[mt], b[nt][0], b[nt][1]);           \
        }                                                                       \
    } while (0)

    int KT = K / 32;   // 24 or 120 (>= 4)
    LOAD_STAGE(0, 0);
    LOAD_STAGE(1, 1);
    LOAD_STAGE(2, 2);

    for (int kt = 0; kt < KT - 3; kt++) {
        asm volatile("cp.async.wait_group 2;" ::: "memory");
        __syncthreads();
        LOAD_STAGE((kt + 3) & 3, kt + 3);
        COMPUTE_STAGE(kt & 3);
    }
    asm volatile("cp.async.wait_group 2;" ::: "memory");
    __syncthreads();
    COMPUTE_STAGE((KT - 3) & 3);
    asm volatile("cp.async.wait_group 1;" ::: "memory");
    __syncthreads();
    COMPUTE_STAGE((KT - 2) & 3);
    asm volatile("cp.async.wait_group 0;" ::: "memory");
    __syncthreads();
    COMPUTE_STAGE((KT - 1) & 3);

    #pragma unroll
    for (int mt = 0; mt < 4; mt++) {
        #pragma unroll
        for (int nt = 0; nt < 4; nt++) {
            int row0 = bm + wm + mt * 16 + grp;
            int col  = bn + wn + nt * 8 + tq * 2;
            #pragma unroll
            for (int half = 0; half < 2; half++) {
                int row = row0 + half * 8;
                float v0 = acc[mt][nt][half * 2 + 0];
                float v1 = acc[mt][nt][half * 2 + 1];
                if (mode == 0) {
                    v0 += bias1[col]; v1 += bias1[col + 1];
                    if (col < QKV) {
                        __nv_bfloat162 h = __floats2bfloat162_rn(v0, v1);
                        *(unsigned*)&g_projb[(size_t)row * QKV + col] = *(unsigned*)&h;
                    } else {
                        __nv_bfloat162 h = __floats2bfloat162_rn(gelu_exact(v0), gelu_exact(v1));
                        *(unsigned*)&g_cat[(size_t)row * CAT + col - 1536] = *(unsigned*)&h;
                    }
                } else {
                    size_t p = (size_t)row * C + col;
                    outp[p]     = xres[p]     + gamma[col]     * (v0 + bias1[col]     + bias2[col]);
                    outp[p + 1] = xres[p + 1] + gamma[col + 1] * (v1 + bias1[col + 1] + bias2[col + 1]);
                }
            }
        }
    }
}

// ---------------- 3. FUSED axial attention (both axes, one kernel) ----------
#define QST 72   // bf16 row stride (64 + 8 pad)

__global__ void __launch_bounds__(128) attn_fused(const float* __restrict__ qw,
                                                  const float* __restrict__ kw) {
    __shared__ __align__(16) __nv_bfloat16 Qs[64 * QST];  // Q (pre-scaled), later V^T
    __shared__ __align__(16) __nv_bfloat16 Ks[64 * QST];  // K
    int head = blockIdx.x % HEADS;
    int line = (blockIdx.x / HEADS) % 64;
    int b    = blockIdx.x / (HEADS * 64);
    int tid  = threadIdx.x, lane = tid & 31, warp = tid >> 5;
    int grp = lane >> 2, tq = lane & 3;
    int row0 = warp * 16;

    float o[8][4];
    #pragma unroll
    for (int nt = 0; nt < 8; nt++)
        #pragma unroll
        for (int j = 0; j < 4; j++) o[nt][j] = 0.f;

    #pragma unroll
    for (int axis = 0; axis < 2; axis++) {
        #define TOKA(pos) (axis == 0 ? ((b * 64 + line) * 64 + (pos)) : ((b * 64 + (pos)) * 64 + line))

        // ---- Q then K: load + per-head LN (2 threads/row, 32 elems each) ----
        {
            int row = tid >> 1, seg = tid & 1;
            const __nv_bfloat16* gq = g_projb + (size_t)TOKA(row) * QKV + head * HDIM + seg * 32;
            {
                float q[32];
                #pragma unroll
                for (int i = 0; i < 4; i++) {
                    uint4 u = *(const uint4*)(gq + i * 8);
                    const __nv_bfloat162* p2 = (const __nv_bfloat162*)&u;
                    #pragma unroll
                    for (int j = 0; j < 4; j++) {
                        float2 f = __bfloat1622float2(p2[j]);
                        q[i*8 + j*2] = f.x; q[i*8 + j*2 + 1] = f.y;
                    }
                }
                float s1 = 0.f, s2 = 0.f;
                #pragma unroll
                for (int e = 0; e < 32; e++) { s1 += q[e]; s2 += q[e]*q[e]; }
                s1 += __shfl_xor_sync(0xFFFFFFFFu, s1, 1);
                s2 += __shfl_xor_sync(0xFFFFFFFFu, s2, 1);
                float mu = s1 * (1.f/64.f);
                float inv = rsqrtf(s2 * (1.f/64.f) - mu * mu + 1e-5f) * 0.125f;
                #pragma unroll
                for (int e = 0; e < 32; e += 2) {
                    int c = seg * 32 + e;
                    __nv_bfloat162 h = __floats2bfloat162_rn((q[e] - mu) * inv * __ldg(qw + c),
                                                             (q[e+1] - mu) * inv * __ldg(qw + c + 1));
                    *(unsigned*)&Qs[row * QST + c] = *(unsigned*)&h;
                }
            }
            {
                float k[32];
                #pragma unroll
                for (int i = 0; i < 4; i++) {
                    uint4 u = *(const uint4*)(gq + C + i * 8);
                    const __nv_bfloat162* p2 = (const __nv_bfloat162*)&u;
                    #pragma unroll
                    for (int j = 0; j < 4; j++) {
                        float2 f = __bfloat1622float2(p2[j]);
                        k[i*8 + j*2] = f.x; k[i*8 + j*2 + 1] = f.y;
                    }
                }
                float s1 = 0.f, s2 = 0.f;
                #pragma unroll
                for (int e = 0; e < 32; e++) { s1 += k[e]; s2 += k[e]*k[e]; }
                s1 += __shfl_xor_sync(0xFFFFFFFFu, s1, 1);
                s2 += __shfl_xor_sync(0xFFFFFFFFu, s2, 1);
                float mu = s1 * (1.f/64.f);
                float inv = rsqrtf(s2 * (1.f/64.f) - mu * mu + 1e-5f);
                #pragma unroll
                for (int e = 0; e < 32; e += 2) {
                    int c = seg * 32 + e;
                    __nv_bfloat162 h = __floats2bfloat162_rn((k[e] - mu) * inv * __ldg(kw + c),
                                                             (k[e+1] - mu) * inv * __ldg(kw + c + 1));
                    *(unsigned*)&Ks[row * QST + c] = *(unsigned*)&h;
                }
            }
        }
        __syncthreads();

        // ---- S = Q K^T ----
        float s[8][4];
        #pragma unroll
        for (int nt = 0; nt < 8; nt++)
            #pragma unroll
            for (int j = 0; j < 4; j++) s[nt][j] = 0.f;
        #pragma unroll
        for (int kt = 0; kt < 4; kt++) {
            unsigned a[4];
            const __nv_bfloat16* qb = &Qs[(row0 + grp) * QST + kt * 16 + tq * 2];
            a[0] = *(const unsigned*)(qb);
            a[1] = *(const unsigned*)(qb + 8 * QST);
            a[2] = *(const unsigned*)(qb + 8);
            a[3] = *(const unsigned*)(qb + 8 * QST + 8);
            #pragma unroll
            for (int nt = 0; nt < 8; nt++) {
                const __nv_bfloat16* kb = &Ks[(nt * 8 + grp) * QST + kt * 16 + tq * 2];
                unsigned b0 = *(const unsigned*)(kb);
                unsigned b1 = *(const unsigned*)(kb + 8);
                MMA16816(s[nt], a, b0, b1);
            }
        }

        // ---- softmax ----
        float m0 = -1e30f, m1 = -1e30f;
        #pragma unroll
        for (int nt = 0; nt < 8; nt++) {
            m0 = fmaxf(m0, fmaxf(s[nt][0], s[nt][1]));
            m1 = fmaxf(m1, fmaxf(s[nt][2], s[nt][3]));
        }
        #pragma unroll
        for (int oo = 1; oo <= 2; oo <<= 1) {
            m0 = fmaxf(m0, __shfl_xor_sync(0xFFFFFFFFu, m0, oo));
            m1 = fmaxf(m1, __shfl_xor_sync(0xFFFFFFFFu, m1, oo));
        }
        float r0 = 0.f, r1 = 0.f;
        #pragma unroll
        for (int nt = 0; nt < 8; nt++) {
            s[nt][0] = __expf(s[nt][0] - m0); s[nt][1] = __expf(s[nt][1] - m0);
            s[nt][2] = __expf(s[nt][2] - m1); s[nt][3] = __expf(s[nt][3] - m1);
            r0 += s[nt][0] + s[nt][1];
            r1 += s[nt][2] + s[nt][3];
        }
        #pragma unroll
        for (int oo = 1; oo <= 2; oo <<= 1) {
            r0 += __shfl_xor_sync(0xFFFFFFFFu, r0, oo);
            r1 += __shfl_xor_sync(0xFFFFFFFFu, r1, oo);
        }
        float inv0 = 1.f / r0, inv1 = 1.f / r1;

        // ---- pack P to bf16 A-fragments ----
        unsigned pf[4][4];
        #pragma unroll
        for (int kt = 0; kt < 4; kt++) {
            __nv_bfloat162 h;
            h = __floats2bfloat162_rn(s[2*kt][0] * inv0, s[2*kt][1] * inv0);     pf[kt][0] = *(unsigned*)&h;
            h = __floats2bfloat162_rn(s[2*kt][2] * inv1, s[2*kt][3] * inv1);     pf[kt][1] = *(unsigned*)&h;
            h = __floats2bfloat162_rn(s[2*kt+1][0] * inv0, s[2*kt+1][1] * inv0); pf[kt][2] = *(unsigned*)&h;
            h = __floats2bfloat162_rn(s[2*kt+1][2] * inv1, s[2*kt+1][3] * inv1); pf[kt][3] = *(unsigned*)&h;
        }

        // ---- Qs dead: load V transposed into it ----
        __syncthreads();
        #pragma unroll
        for (int it = 0; it < 4; it++) {
            int chunk = tid + it * 128;
            int pos = chunk >> 3, c8 = (chunk & 7) * 8;
            uint4 u = *(const uint4*)(g_projb + (size_t)TOKA(pos) * QKV + 2 * C + head * HDIM + c8);
            const __nv_bfloat16* e = (const __nv_bfloat16*)&u;
            #pragma unroll
            for (int j = 0; j < 8; j++)
                Qs[(c8 + j) * QST + pos] = e[j];
        }
        __syncthreads();

        // ---- O += P V ----
        #pragma unroll
        for (int kt = 0; kt < 4; kt++) {
            #pragma unroll
            for (int nt = 0; nt < 8; nt++) {
                const __nv_bfloat16* vb = &Qs[(nt * 8 + grp) * QST + kt * 16 + tq * 2];
                unsigned b0 = *(const unsigned*)(vb);
                unsigned b1 = *(const unsigned*)(vb + 8);
                MMA16816(o[nt], pf[kt], b0, b1);
            }
        }
        __syncthreads();   // protect Qs/Ks before next axis reloads them
        #undef TOKA
    }

    // ---- write combined O (fp32 accumulated across axes) -> g_cat bf16 ----
    #pragma unroll
    for (int half = 0; half < 2; half++) {
        int qrow = row0 + grp + half * 8;
        size_t tok = (size_t)((b * 64 + qrow) * 64 + line);
        #pragma unroll
        for (int nt = 0; nt < 8; nt++) {
            int col = head * HDIM + nt * 8 + tq * 2;
            __nv_bfloat162 h = __floats2bfloat162_rn(o[nt][half * 2 + 0], o[nt][half * 2 + 1]);
            *(unsigned*)&g_cat[tok * CAT + col] = *(unsigned*)&h;
        }
    }
}

// ---------------- launch ----------------------------------------------------
extern "C" void kernel_launch(void* const* d_in, const int* in_sizes, int n_in,
                              void* d_out, int out_size) {
    const float* x      = (const float*)d_in[0];
    const float* norm_w = (const float*)d_in[1];
    const float* Wqkv   = (const float*)d_in[2];
    const float* bqkv   = (const float*)d_in[3];
    const float* qnw    = (const float*)d_in[4];
    const float* knw    = (const float*)d_in[5];
    const float* Wout   = (const float*)d_in[6];
    const float* bout   = (const float*)d_in[7];
    const float* Wmlp   = (const float*)d_in[8];
    const float* bmlp   = (const float*)d_in[9];
    const float* gamma  = (const float*)d_in[10];
    float* out = (float*)d_out;

    void *p_xnb, *p_cat, *p_wq, *p_wc;
    cudaGetSymbolAddress(&p_xnb, g_xn_bf);
    cudaGetSymbolAddress(&p_cat, g_cat);
    cudaGetSymbolAddress(&p_wq,  g_Wqkv_t);
    cudaGetSymbolAddress(&p_wc,  g_Wcat_t);

    cudaFuncSetAttribute(hgemm, cudaFuncAttributeMaxDynamicSharedMemorySize, SMEM_BYTES);

    // 0. transpose+convert weights
    transpose_w<<<dim3(C7 / 32, C / 32), dim3(32, 8)>>>(Wqkv, (__nv_bfloat16*)p_wq, C7, C, 0);
    transpose_w<<<dim3(C / 32, C / 32), dim3(32, 8)>>>(Wout, (__nv_bfloat16*)p_wc, C, CAT, 0);
    transpose_w<<<dim3(C / 32, FFDIM / 32), dim3(32, 8)>>>(Wmlp, (__nv_bfloat16*)p_wc, C, CAT, C);

    // 1. LayerNorm -> bf16 xn (vectorized)
    ln_kernel<<<NTOK, 192>>>(x, norm_w);

    // 2. fused qkv+ff GEMM (q,k,v bf16 -> g_projb; gelu(ff) bf16 -> g_cat)
    hgemm<<<dim3(C7 / BN, NTOK / BM), 256, SMEM_BYTES>>>(
        (const __nv_bfloat16*)p_xnb, C, (const __nv_bfloat16*)p_wq, C,
        C, bqkv, nullptr, nullptr, nullptr, nullptr, 0);

    // 3. fused axial attention (both axes, O accumulated in registers)
    attn_fused<<<Bsz * 64 * HEADS, 128>>>(qnw, knw);

    // 4. fused output GEMM + residual epilogue
    hgemm<<<dim3(C / BN, NTOK / BM), 256, SMEM_BYTES>>>(
        (const __nv_bfloat16*)p_cat, CAT, (const __nv_bfloat16*)p_wc, CAT,
        CAT, bout, bmlp, x, gamma, out, 1);
}